// round 1
// baseline (speedup 1.0000x reference)
#include <cuda_runtime.h>
#include <cuda_bf16.h>

#define N_PATHS 2048
#define N_STEPS 512
#define N_FWD   40
#define DT      (1.0f / 512.0f)
#define SHIFT   0.02f
#define LOG2E   1.4426950408889634f

// ---------------- device scratch (no allocations allowed) ----------------
__device__ float  g_w[N_STEPS];        // Toeplitz kernel weights w[j], j = t-s
__device__ float  g_cw2[N_STEPS];      // prefix sum of w^2 (for var_comp)
__device__ float4 g_fbm4[N_PATHS * N_STEPS];   // fbm4[p][t][0..3], 16.8 MB

// ---------------- f32x2 helpers ----------------
__device__ __forceinline__ unsigned long long f2pack(float lo, float hi) {
    unsigned long long r;
    asm("mov.b64 %0, {%1, %2};" : "=l"(r) : "f"(lo), "f"(hi));
    return r;
}
__device__ __forceinline__ void ffma2(unsigned long long& d, unsigned long long a, unsigned long long b) {
    asm("fma.rn.f32x2 %0, %1, %2, %0;" : "+l"(d) : "l"(a), "l"(b));
}
__device__ __forceinline__ float2 f2unpack(unsigned long long v) {
    float2 r;
    asm("mov.b64 {%0, %1}, %2;" : "=f"(r.x), "=f"(r.y) : "l"(v));
    return r;
}

// ---------------- kernel 1: weights + prefix of w^2 ----------------
// w[j] = ((j+1)^0.6 - j^0.6)/0.6 * DT^(-0.4) / Gamma(0.6)
__global__ void k_weights() {
    int j = threadIdx.x;
    const double GAMMA_C = 1.4891922248812817;   // Gamma(0.6)
    double scale = exp(-0.4 * log(1.0 / 512.0)) / GAMMA_C; // DT^ALPHA / Gamma
    double num = (pow((double)(j + 1), 0.6) - pow((double)j, 0.6)) / 0.6;
    g_w[j] = (float)(num * scale);
    __syncthreads();
    if (j == 0) {
        float acc = 0.f;
        for (int i = 0; i < N_STEPS; i++) {
            float wv = g_w[i];
            acc += wv * wv;
            g_cw2[i] = acc;
        }
    }
}

// ---------------- kernel 2: causal convolution (fBM) ----------------
// fbm4[p,t,d] = sum_{s<=t} w[t-s] * dz[p,s,d], d = 0..3
// One block = 2 paths, 512 threads (thread = t). dz packed in shared as
// two f32x2 words per step; inner loop uses packed FMAs.
__global__ __launch_bounds__(512) void k_conv(const float* __restrict__ dz) {
    __shared__ ulonglong2 sdz0[N_STEPS];
    __shared__ ulonglong2 sdz1[N_STEPS];
    __shared__ float sw[N_STEPS];

    int p0 = blockIdx.x * 2;
    int t  = threadIdx.x;

    const float4* dzv = (const float4*)dz;
    float4 d0 = dzv[(size_t)p0 * N_STEPS + t];
    float4 d1 = dzv[(size_t)(p0 + 1) * N_STEPS + t];
    ulonglong2 u0, u1;
    u0.x = f2pack(d0.x, d0.y); u0.y = f2pack(d0.z, d0.w);
    u1.x = f2pack(d1.x, d1.y); u1.y = f2pack(d1.z, d1.w);
    sdz0[t] = u0;
    sdz1[t] = u1;
    sw[t] = g_w[t];
    __syncthreads();

    unsigned long long a01 = 0ull, a23 = 0ull;  // path p0 accum {f0,f1},{f2,f3}
    unsigned long long b01 = 0ull, b23 = 0ull;  // path p0+1

    int lo = t & ~31;  // warp-uniform: s <= lo is valid for every lane of this warp

    #pragma unroll 4
    for (int s = 0; s <= lo; ++s) {
        ulonglong2 x = sdz0[s];
        ulonglong2 y = sdz1[s];
        float wv = sw[t - s];
        unsigned long long ww = f2pack(wv, wv);
        ffma2(a01, x.x, ww);
        ffma2(a23, x.y, ww);
        ffma2(b01, y.x, ww);
        ffma2(b23, y.y, ww);
    }
    // guarded tail (<= 31 iterations, intra-warp triangular edge)
    for (int s = lo + 1; s < lo + 32; ++s) {
        if (s <= t) {
            ulonglong2 x = sdz0[s];
            ulonglong2 y = sdz1[s];
            float wv = sw[t - s];
            unsigned long long ww = f2pack(wv, wv);
            ffma2(a01, x.x, ww);
            ffma2(a23, x.y, ww);
            ffma2(b01, y.x, ww);
            ffma2(b23, y.y, ww);
        }
    }

    float2 r01 = f2unpack(a01), r23 = f2unpack(a23);
    float2 s01 = f2unpack(b01), s23 = f2unpack(b23);
    g_fbm4[(size_t)p0 * N_STEPS + t]       = make_float4(r01.x, r01.y, r23.x, r23.y);
    g_fbm4[(size_t)(p0 + 1) * N_STEPS + t] = make_float4(s01.x, s01.y, s23.x, s23.y);
}

// ---------------- kernel 3: per-(path, fwd) sequential scan ----------------
// thread = (p, n); serial cumsum over t (matches reference rounding order).
__global__ __launch_bounds__(128) void k_path(
    const float* __restrict__ dz,
    const float* __restrict__ F0,
    const float* __restrict__ alphas,
    const float* __restrict__ rhos,
    const float* __restrict__ nus,
    const float* __restrict__ tau,
    const float* __restrict__ L,
    const float* __restrict__ Lam,
    float* __restrict__ out)
{
    __shared__ float scw[N_STEPS];
    for (int i = threadIdx.x; i < N_STEPS; i += blockDim.x) scw[i] = g_cw2[i];
    __syncthreads();

    int tid = blockIdx.x * blockDim.x + threadIdx.x;   // 0 .. 81919
    int p = tid / N_FWD;
    int n = tid - p * N_FWD;

    float f0n = F0[n];
    float vs  = alphas[n] * sqrtf(fabsf(f0n + SHIFT));  // vol_scale[n]
    float rho = rhos[n];
    float nu  = nus[n];
    float sq  = sqrtf(fmaxf(1.f - rho * rho, 0.f));

    float l0 = L[n * 3 + 0], l1 = L[n * 3 + 1], l2 = L[n * 3 + 2];
    // exponent: log2(unit_vols) = a0*f0+a1*f1+a2*f2+a3*f3 - bb*cw2[t]
    float a0 = nu * rho * l0 * LOG2E;
    float a1 = nu * rho * l1 * LOG2E;
    float a2 = nu * rho * l2 * LOG2E;
    float a3 = nu * sq * LOG2E;
    float bb = 0.5f * nu * nu * DT * LOG2E;
    // wr * vol_scale folded into loadings
    float w0 = vs * l0, w1 = vs * l1, w2 = vs * l2;

    // mu_0[n] = -vs[n] * sum_m Lam[n,m] * omega0[m]
    float mdot = 0.f;
    for (int m = 0; m < N_FWD; ++m) {
        float f0m = F0[m];
        float vsm = alphas[m] * sqrtf(fabsf(f0m + SHIFT));
        float om  = tau[m] * vsm / (1.f + tau[m] * f0m);
        mdot = fmaf(Lam[n * N_FWD + m], om, mdot);
    }
    float mu0dt = -vs * mdot * DT;

    float acc = f0n;
    float* op = out + (size_t)p * 513 * N_FWD + n;
    *op = acc;   // row 0 = F0

    const float4* fb  = &g_fbm4[(size_t)p * N_STEPS];
    const float4* dzp = (const float4*)dz + (size_t)p * N_STEPS;

    #pragma unroll 4
    for (int t = 0; t < N_STEPS; ++t) {
        float4 f = fb[t];
        float4 d = dzp[t];
        float arg = fmaf(a0, f.x,
                    fmaf(a1, f.y,
                    fmaf(a2, f.z,
                    fmaf(a3, f.w, -bb * scw[t]))));
        float uv;
        asm("ex2.approx.f32 %0, %1;" : "=f"(uv) : "f"(arg));  // unit_vols
        float wr = fmaf(w0, d.x, fmaf(w1, d.y, w2 * d.z));    // vs * wr
        // dF = mu0*uv^2*DT + wr*uv*vs = uv * (mu0dt*uv + vs*wr)
        acc = fmaf(uv, fmaf(mu0dt, uv, wr), acc);
        op += N_FWD;
        *op = acc;   // row t+1
    }
}

extern "C" void kernel_launch(void* const* d_in, const int* in_sizes, int n_in,
                              void* d_out, int out_size) {
    const float* dz     = (const float*)d_in[0];
    const float* F0     = (const float*)d_in[1];
    const float* alphas = (const float*)d_in[2];
    const float* rhos   = (const float*)d_in[3];
    const float* nus    = (const float*)d_in[4];
    const float* tau    = (const float*)d_in[5];
    const float* L      = (const float*)d_in[6];
    const float* Lam    = (const float*)d_in[7];
    float* out = (float*)d_out;

    k_weights<<<1, N_STEPS>>>();
    k_conv<<<N_PATHS / 2, N_STEPS>>>(dz);
    k_path<<<(N_PATHS * N_FWD) / 128, 128>>>(dz, F0, alphas, rhos, nus, tau, L, Lam, out);
}

// round 2
// speedup vs baseline: 1.1648x; 1.1648x over previous
#include <cuda_runtime.h>
#include <cuda_bf16.h>

#define N_PATHS 2048
#define N_STEPS 512
#define N_FWD   40
#define DT      (1.0f / 512.0f)
#define SHIFT   0.02f
#define LOG2E   1.4426950408889634f

// ---------------- device scratch ----------------
__device__ float  g_w[N_STEPS];                 // Toeplitz weights w[j]
__device__ float  g_cw2[N_STEPS];               // inclusive prefix sum of w^2
__device__ float4 g_fbm4[N_PATHS * N_STEPS];    // fbm4[p][t][0..3]

// ---------------- f32x2 helpers ----------------
__device__ __forceinline__ unsigned long long f2pack(float lo, float hi) {
    unsigned long long r;
    asm("mov.b64 %0, {%1, %2};" : "=l"(r) : "f"(lo), "f"(hi));
    return r;
}
__device__ __forceinline__ void ffma2(unsigned long long& d, unsigned long long a, unsigned long long b) {
    asm("fma.rn.f32x2 %0, %1, %2, %0;" : "+l"(d) : "l"(a), "l"(b));
}
__device__ __forceinline__ float2 f2unpack(unsigned long long v) {
    float2 r;
    asm("mov.b64 {%0, %1}, %2;" : "=f"(r.x), "=f"(r.y) : "l"(v));
    return r;
}

// ---------------- kernel 1: weights + parallel prefix of w^2 ----------------
// w[j] = ((j+1)^0.6 - j^0.6)/0.6 * DT^(-0.4) / Gamma(0.6)
// Cancellation-free: (j+1)^0.6 - j^0.6 = j^0.6 * expm1(0.6*log1p(1/j))
__global__ __launch_bounds__(512) void k_init() {
    __shared__ float sc[N_STEPS];
    int j = threadIdx.x;

    // scale = 2^3.6 / Gamma(0.6), computed once in double (cheap, 512 lanes parallel)
    const double scale_d = exp(3.6 * 0.6931471805599453) / 1.4891922248812817;
    float scale = (float)scale_d;

    float num;
    if (j == 0) {
        num = 1.0f / 0.6f;
    } else {
        float fj  = (float)j;
        float p6  = exp2f(0.6f * log2f(fj));              // j^0.6
        float em  = expm1f(0.6f * log1pf(1.0f / fj));     // (1+1/j)^0.6 - 1
        num = p6 * em * (1.0f / 0.6f);
    }
    float w = num * scale;
    g_w[j] = w;

    // Hillis-Steele inclusive scan of w^2 (9 steps)
    sc[j] = w * w;
    __syncthreads();
    #pragma unroll
    for (int off = 1; off < N_STEPS; off <<= 1) {
        float v = sc[j];
        if (j >= off) v += sc[j - off];
        __syncthreads();
        sc[j] = v;
        __syncthreads();
    }
    g_cw2[j] = sc[j];
}

// ---------------- kernel 2: causal Toeplitz convolution (fBM) ----------------
// fbm4[p,t,d] = sum_{s<=t} w[t-s] * dz[p,s,d].  4 paths per block; thread = t.
// dz packed in shared as f32x2 pairs; w pre-packed (w,w) -> no pack mov in loop.
__global__ __launch_bounds__(512, 2) void k_conv(const float* __restrict__ dz) {
    __shared__ ulonglong2 sdz[4][N_STEPS];          // 32 KB
    __shared__ unsigned long long sw2[N_STEPS];     //  4 KB

    int p0 = blockIdx.x * 4;
    int t  = threadIdx.x;

    const float4* dzv = (const float4*)dz;
    #pragma unroll
    for (int q = 0; q < 4; ++q) {
        float4 d = dzv[(size_t)(p0 + q) * N_STEPS + t];
        ulonglong2 u;
        u.x = f2pack(d.x, d.y);
        u.y = f2pack(d.z, d.w);
        sdz[q][t] = u;
    }
    float wv = g_w[t];
    sw2[t] = f2pack(wv, wv);
    __syncthreads();

    unsigned long long acc01[4] = {0ull, 0ull, 0ull, 0ull};
    unsigned long long acc23[4] = {0ull, 0ull, 0ull, 0ull};

    int lo = t & ~31;  // warp-uniform trip count

    #pragma unroll 4
    for (int s = 0; s <= lo; ++s) {
        unsigned long long ww = sw2[t - s];
        #pragma unroll
        for (int q = 0; q < 4; ++q) {
            ulonglong2 x = sdz[q][s];
            ffma2(acc01[q], x.x, ww);
            ffma2(acc23[q], x.y, ww);
        }
    }
    // intra-warp triangular edge: <=31 guarded iterations
    #pragma unroll
    for (int d = 1; d < 32; ++d) {
        int s = lo + d;
        if (s <= t) {
            unsigned long long ww = sw2[t - s];
            #pragma unroll
            for (int q = 0; q < 4; ++q) {
                ulonglong2 x = sdz[q][s];
                ffma2(acc01[q], x.x, ww);
                ffma2(acc23[q], x.y, ww);
            }
        }
    }

    #pragma unroll
    for (int q = 0; q < 4; ++q) {
        float2 r01 = f2unpack(acc01[q]);
        float2 r23 = f2unpack(acc23[q]);
        g_fbm4[(size_t)(p0 + q) * N_STEPS + t] = make_float4(r01.x, r01.y, r23.x, r23.y);
    }
}

// ---------------- kernel 3: per-(path, fwd) sequential scan ----------------
__global__ __launch_bounds__(256) void k_path(
    const float* __restrict__ dz,
    const float* __restrict__ F0,
    const float* __restrict__ alphas,
    const float* __restrict__ rhos,
    const float* __restrict__ nus,
    const float* __restrict__ tau,
    const float* __restrict__ L,
    const float* __restrict__ Lam,
    float* __restrict__ out)
{
    __shared__ float scw[N_STEPS];
    for (int i = threadIdx.x; i < N_STEPS; i += blockDim.x) scw[i] = g_cw2[i];
    __syncthreads();

    int tid = blockIdx.x * blockDim.x + threadIdx.x;   // 0 .. 81919
    int p = tid / N_FWD;
    int n = tid - p * N_FWD;

    float f0n = F0[n];
    float vs  = alphas[n] * sqrtf(fabsf(f0n + SHIFT));  // vol_scale[n]
    float rho = rhos[n];
    float nu  = nus[n];
    float sq  = sqrtf(fmaxf(1.f - rho * rho, 0.f));

    float l0 = L[n * 3 + 0], l1 = L[n * 3 + 1], l2 = L[n * 3 + 2];
    float a0 = nu * rho * l0 * LOG2E;
    float a1 = nu * rho * l1 * LOG2E;
    float a2 = nu * rho * l2 * LOG2E;
    float a3 = nu * sq * LOG2E;
    float bb = 0.5f * nu * nu * DT * LOG2E;
    float w0 = vs * l0, w1 = vs * l1, w2 = vs * l2;

    // mu_0[n]*DT = -vs[n] * (Lam @ omega0)[n] * DT
    float mdot = 0.f;
    for (int m = 0; m < N_FWD; ++m) {
        float f0m = F0[m];
        float vsm = alphas[m] * sqrtf(fabsf(f0m + SHIFT));
        float om  = tau[m] * vsm / (1.f + tau[m] * f0m);
        mdot = fmaf(Lam[n * N_FWD + m], om, mdot);
    }
    float mu0dt = -vs * mdot * DT;

    float acc = f0n;
    float* op = out + (size_t)p * 513 * N_FWD + n;
    __stcs(op, acc);   // row 0 = F0

    const float4* fb  = &g_fbm4[(size_t)p * N_STEPS];
    const float4* dzp = (const float4*)dz + (size_t)p * N_STEPS;

    #pragma unroll 4
    for (int t = 0; t < N_STEPS; ++t) {
        float4 f = fb[t];
        float4 d = dzp[t];
        float arg = fmaf(a0, f.x,
                    fmaf(a1, f.y,
                    fmaf(a2, f.z,
                    fmaf(a3, f.w, -bb * scw[t]))));
        float uv;
        asm("ex2.approx.f32 %0, %1;" : "=f"(uv) : "f"(arg));  // unit_vols
        float wr = fmaf(w0, d.x, fmaf(w1, d.y, w2 * d.z));    // vs * wr
        acc = fmaf(uv, fmaf(mu0dt, uv, wr), acc);             // dF = uv*(mu0dt*uv + vs*wr)
        op += N_FWD;
        __stcs(op, acc);   // row t+1
    }
}

extern "C" void kernel_launch(void* const* d_in, const int* in_sizes, int n_in,
                              void* d_out, int out_size) {
    const float* dz     = (const float*)d_in[0];
    const float* F0     = (const float*)d_in[1];
    const float* alphas = (const float*)d_in[2];
    const float* rhos   = (const float*)d_in[3];
    const float* nus    = (const float*)d_in[4];
    const float* tau    = (const float*)d_in[5];
    const float* L      = (const float*)d_in[6];
    const float* Lam    = (const float*)d_in[7];
    float* out = (float*)d_out;

    k_init<<<1, N_STEPS>>>();
    k_conv<<<N_PATHS / 4, N_STEPS>>>(dz);
    k_path<<<(N_PATHS * N_FWD) / 256, 256>>>(dz, F0, alphas, rhos, nus, tau, L, Lam, out);
}

// round 3
// speedup vs baseline: 1.2461x; 1.0698x over previous
#include <cuda_runtime.h>
#include <cuda_bf16.h>

#define N_PATHS 2048
#define N_STEPS 512
#define N_FWD   40
#define DT      (1.0f / 512.0f)
#define SHIFT   0.02f
#define LOG2E   1.4426950408889634f

// ---------------- device scratch ----------------
__device__ float  g_cw2[N_STEPS];               // inclusive prefix sum of w^2
__device__ float4 g_fbm4[N_PATHS * N_STEPS];    // fbm4[p][t][0..3]

// ---------------- f32x2 helpers ----------------
__device__ __forceinline__ unsigned long long f2pack(float lo, float hi) {
    unsigned long long r;
    asm("mov.b64 %0, {%1, %2};" : "=l"(r) : "f"(lo), "f"(hi));
    return r;
}
__device__ __forceinline__ void ffma2(unsigned long long& d, unsigned long long a, unsigned long long b) {
    asm("fma.rn.f32x2 %0, %1, %2, %0;" : "+l"(d) : "l"(a), "l"(b));
}
__device__ __forceinline__ float2 f2unpack(unsigned long long v) {
    float2 r;
    asm("mov.b64 {%0, %1}, %2;" : "=f"(r.x), "=f"(r.y) : "l"(v));
    return r;
}

// Toeplitz weight, cancellation-free in fp32:
// w[j] = ((j+1)^0.6 - j^0.6)/0.6 * 2^3.6 / Gamma(0.6)
__device__ __forceinline__ float toeplitz_w(int j) {
    const float scale = 12.125732f / 1.4891922f;   // 2^3.6 / Gamma(0.6)
    float num;
    if (j == 0) {
        num = 1.0f / 0.6f;
    } else {
        float fj = (float)j;
        float p6 = exp2f(0.6f * log2f(fj));            // j^0.6
        float em = expm1f(0.6f * log1pf(1.0f / fj));   // (1+1/j)^0.6 - 1
        num = p6 * em * (1.0f / 0.6f);
    }
    return num * scale;
}

// Warp -> t-block permutation balancing trip counts across SMSPs.
// SMSP k owns warps {k, k+4, k+8, k+12}; each set of t-blocks sums to 30.
__device__ __constant__ int c_tb[16] = {0, 2, 4, 6, 15, 13, 11, 9,
                                        1, 3, 5, 7, 14, 12, 10, 8};

// ---------------- kernel 1: causal Toeplitz convolution (fBM) ----------------
// fbm4[p,t,d] = sum_{s<=t} w[t-s] * dz[p,s,d].  4 paths per block.
// Weights computed in-block (no separate init kernel). Block 0 also emits g_cw2.
__global__ __launch_bounds__(512, 2) void k_conv(const float* __restrict__ dz) {
    __shared__ ulonglong2 sdz[4][N_STEPS];          // 32 KB
    __shared__ unsigned long long sw2[N_STEPS];     //  4 KB
    __shared__ float scw[N_STEPS];                  //  2 KB (scan scratch, block 0)

    int p0   = blockIdx.x * 4;
    int wid  = threadIdx.x >> 5;
    int lane = threadIdx.x & 31;
    int t    = c_tb[wid] * 32 + lane;    // permuted t assignment

    // per-block weight compute (cheap MUFU math), indexed by this thread's t
    float wv = toeplitz_w(t);
    sw2[t] = f2pack(wv, wv);

    const float4* dzv = (const float4*)dz;
    #pragma unroll
    for (int q = 0; q < 4; ++q) {
        float4 d = dzv[(size_t)(p0 + q) * N_STEPS + t];
        ulonglong2 u;
        u.x = f2pack(d.x, d.y);
        u.y = f2pack(d.z, d.w);
        sdz[q][t] = u;
    }

    // block 0: parallel scan of w^2 -> g_cw2 (consumed by k_path, launched after)
    if (blockIdx.x == 0) {
        scw[t] = wv * wv;
        __syncthreads();
        #pragma unroll
        for (int off = 1; off < N_STEPS; off <<= 1) {
            float v = scw[t];
            if (t >= off) v += scw[t - off];
            __syncthreads();
            scw[t] = v;
            __syncthreads();
        }
        g_cw2[t] = scw[t];
    }
    __syncthreads();

    unsigned long long acc01[4] = {0ull, 0ull, 0ull, 0ull};
    unsigned long long acc23[4] = {0ull, 0ull, 0ull, 0ull};

    int lo = t & ~31;   // warp-uniform trip count (t's low 5 bits = lane)

    #pragma unroll 4
    for (int s = 0; s <= lo; ++s) {
        unsigned long long ww = sw2[t - s];
        #pragma unroll
        for (int q = 0; q < 4; ++q) {
            ulonglong2 x = sdz[q][s];
            ffma2(acc01[q], x.x, ww);
            ffma2(acc23[q], x.y, ww);
        }
    }
    // intra-warp triangular edge: <=31 guarded iterations
    #pragma unroll
    for (int d = 1; d < 32; ++d) {
        int s = lo + d;
        if (s <= t) {
            unsigned long long ww = sw2[t - s];
            #pragma unroll
            for (int q = 0; q < 4; ++q) {
                ulonglong2 x = sdz[q][s];
                ffma2(acc01[q], x.x, ww);
                ffma2(acc23[q], x.y, ww);
            }
        }
    }

    #pragma unroll
    for (int q = 0; q < 4; ++q) {
        float2 r01 = f2unpack(acc01[q]);
        float2 r23 = f2unpack(acc23[q]);
        g_fbm4[(size_t)(p0 + q) * N_STEPS + t] = make_float4(r01.x, r01.y, r23.x, r23.y);
    }
}

// ---------------- kernel 2: per-(path, fwd-pair) sequential scan ----------------
// thread = (p, n0=2j); handles forwards n0 and n0+1. float2 streaming stores.
__global__ __launch_bounds__(256) void k_path(
    const float* __restrict__ dz,
    const float* __restrict__ F0,
    const float* __restrict__ alphas,
    const float* __restrict__ rhos,
    const float* __restrict__ nus,
    const float* __restrict__ tau,
    const float* __restrict__ L,
    const float* __restrict__ Lam,
    float* __restrict__ out)
{
    __shared__ float scw[N_STEPS];
    for (int i = threadIdx.x; i < N_STEPS; i += blockDim.x) scw[i] = g_cw2[i];
    __syncthreads();

    int tid = blockIdx.x * blockDim.x + threadIdx.x;   // 0 .. 40959
    int p  = tid / (N_FWD / 2);
    int j  = tid - p * (N_FWD / 2);
    int n0 = 2 * j;

    // per-n constants for the two forwards
    float a0[2], a1[2], a2[2], a3[2], bb[2], w0[2], w1[2], w2[2], mu0dt[2], acc[2];
    float vsn[2];
    #pragma unroll
    for (int e = 0; e < 2; ++e) {
        int n = n0 + e;
        float f0n = F0[n];
        float vs  = alphas[n] * sqrtf(fabsf(f0n + SHIFT));
        float rho = rhos[n];
        float nu  = nus[n];
        float sq  = sqrtf(fmaxf(1.f - rho * rho, 0.f));
        float l0 = L[n * 3 + 0], l1 = L[n * 3 + 1], l2 = L[n * 3 + 2];
        a0[e] = nu * rho * l0 * LOG2E;
        a1[e] = nu * rho * l1 * LOG2E;
        a2[e] = nu * rho * l2 * LOG2E;
        a3[e] = nu * sq * LOG2E;
        bb[e] = 0.5f * nu * nu * DT * LOG2E;
        w0[e] = vs * l0; w1[e] = vs * l1; w2[e] = vs * l2;
        vsn[e] = vs;
        acc[e] = f0n;
    }
    // mu_0[n]*DT = -vs[n] * (Lam @ omega0)[n] * DT
    #pragma unroll
    for (int e = 0; e < 2; ++e) mu0dt[e] = 0.f;
    for (int m = 0; m < N_FWD; ++m) {
        float f0m = F0[m];
        float vsm = alphas[m] * sqrtf(fabsf(f0m + SHIFT));
        float om  = tau[m] * vsm / (1.f + tau[m] * f0m);
        mu0dt[0] = fmaf(Lam[(n0    ) * N_FWD + m], om, mu0dt[0]);
        mu0dt[1] = fmaf(Lam[(n0 + 1) * N_FWD + m], om, mu0dt[1]);
    }
    #pragma unroll
    for (int e = 0; e < 2; ++e) mu0dt[e] *= -vsn[e] * DT;

    float* op = out + (size_t)p * 513 * N_FWD + n0;
    __stcs((float2*)op, make_float2(acc[0], acc[1]));   // row 0 = F0

    const float4* fb  = &g_fbm4[(size_t)p * N_STEPS];
    const float4* dzp = (const float4*)dz + (size_t)p * N_STEPS;

    #pragma unroll 4
    for (int t = 0; t < N_STEPS; ++t) {
        float4 f = fb[t];
        float4 d = dzp[t];
        float cw = scw[t];
        #pragma unroll
        for (int e = 0; e < 2; ++e) {
            float arg = fmaf(a0[e], f.x,
                        fmaf(a1[e], f.y,
                        fmaf(a2[e], f.z,
                        fmaf(a3[e], f.w, -bb[e] * cw))));
            float uv;
            asm("ex2.approx.f32 %0, %1;" : "=f"(uv) : "f"(arg));   // unit_vols
            float wr = fmaf(w0[e], d.x, fmaf(w1[e], d.y, w2[e] * d.z));
            acc[e] = fmaf(uv, fmaf(mu0dt[e], uv, wr), acc[e]);
        }
        op += N_FWD;
        __stcs((float2*)op, make_float2(acc[0], acc[1]));   // row t+1
    }
}

extern "C" void kernel_launch(void* const* d_in, const int* in_sizes, int n_in,
                              void* d_out, int out_size) {
    const float* dz     = (const float*)d_in[0];
    const float* F0     = (const float*)d_in[1];
    const float* alphas = (const float*)d_in[2];
    const float* rhos   = (const float*)d_in[3];
    const float* nus    = (const float*)d_in[4];
    const float* tau    = (const float*)d_in[5];
    const float* L      = (const float*)d_in[6];
    const float* Lam    = (const float*)d_in[7];
    float* out = (float*)d_out;

    k_conv<<<N_PATHS / 4, N_STEPS>>>(dz);
    k_path<<<(N_PATHS * (N_FWD / 2)) / 256, 256>>>(dz, F0, alphas, rhos, nus, tau, L, Lam, out);
}